// round 9
// baseline (speedup 1.0000x reference)
#include <cuda_runtime.h>
#include <cuda_fp16.h>
#include <cstdint>

namespace {
constexpr int  Bn = 8;
constexpr long Tn = 262144;
constexpr long Sn = 131072;   // output positions
constexpr int  En = 128;      // conv channels = GEMM K
constexpr int  Pn = 64;       // out features  = GEMM N
constexpr int  S_TILE = 128;  // GEMM M per CTA (4 warps x m32)
constexpr int  THREADS = 128;
constexpr int  LDA = 136;     // halves/row, padded -> conflict-free ldmatrix

constexpr int SMEM_TOTAL = S_TILE * LDA * 2;   // 34816 B
}

// B fragments, lane-contiguous: [G(2)][chunk(8)][pair(2)][lane(32)] of uint4
__device__ uint4 g_bfrag[2 * 8 * 2 * 32];

__device__ __forceinline__ uint32_t smem_u32(const void* p) {
    return (uint32_t)__cvta_generic_to_shared(p);
}

#define LDSM_X4(r0, r1, r2, r3, addr)                                            \
    asm volatile("ldmatrix.sync.aligned.m8n8.x4.shared.b16 {%0,%1,%2,%3}, [%4];" \
                 : "=r"(r0), "=r"(r1), "=r"(r2), "=r"(r3) : "r"(addr))

#define MMA16816(d, a0, a1, a2, a3, b0, b1)                                      \
    asm volatile("mma.sync.aligned.m16n8k16.row.col.f32.f16.f16.f32 "            \
                 "{%0,%1,%2,%3},{%4,%5,%6,%7},{%8,%9},{%0,%1,%2,%3};"            \
                 : "+f"((d)[0]), "+f"((d)[1]), "+f"((d)[2]), "+f"((d)[3])        \
                 : "r"(a0), "r"(a1), "r"(a2), "r"(a3), "r"(b0), "r"(b1))

// ---- init: pack lin_w (fp32 [64,128]) into fp16 B fragments ----
// N-permutation: logical col = 32*G + (vn>>1)*8 + nt*2 + (vn&1) so each
// D-fragment thread owns 8 consecutive output columns per row (per G half).
__global__ void pack_w_kernel(const float* __restrict__ lin_w) {
    const int idx = blockIdx.x * blockDim.x + threadIdx.x;   // 512 threads
    if (idx >= 2 * 8 * 32) return;
    const int lane  = idx & 31;
    const int chunk = (idx >> 5) & 7;
    const int G     = idx >> 8;

    uint32_t r[8];
#pragma unroll
    for (int s = 0; s < 2; s++) {          // reg pair (np)
#pragma unroll
        for (int q = 0; q < 4; q++) {
            const int nt = 2 * s + (q >> 1);                 // n8 tile index 0..3
            const int n  = 32 * G + (lane >> 3) * 8 + nt * 2 + ((lane >> 2) & 1);
            const int k  = 16 * chunk + ((q & 1) << 3) + ((lane & 3) << 1);
            const float2 w = *reinterpret_cast<const float2*>(lin_w + n * En + k);
            __half2 h = __halves2half2(__float2half_rn(w.x), __float2half_rn(w.y));
            r[s * 4 + q] = *reinterpret_cast<const uint32_t*>(&h);
        }
    }
    g_bfrag[((G * 8 + chunk) * 2 + 0) * 32 + lane] = make_uint4(r[0], r[1], r[2], r[3]);
    g_bfrag[((G * 8 + chunk) * 2 + 1) * 32 + lane] = make_uint4(r[4], r[5], r[6], r[7]);
}

__global__ void __launch_bounds__(THREADS, 5)
encoder_kernel(const float* __restrict__ x,       // [B, T]
               const float* __restrict__ conv_w,  // [128, 1, 5]
               const float* __restrict__ conv_b,  // [128]
               const float* __restrict__ lin_b,   // [64]
               float* __restrict__ out)           // [B, S, 64]
{
    extern __shared__ char smem[];

    const int tid  = threadIdx.x;
    const int wid  = tid >> 5;
    const int lane = tid & 31;
    const int b    = blockIdx.y;
    const int s0   = blockIdx.x * S_TILE;

    // each warp owns rows 32*wid..32*wid+31 (conv producer AND GEMM consumer)
    __half* fw = (__half*)smem + wid * 32 * LDA;

    // ---- conv taps: 4 channels per lane (vectorized loads) ----
    const int c0 = 4 * lane;
    float w[4][5], cb[4];
    {
        const float4* cw4 = reinterpret_cast<const float4*>(conv_w + 5 * c0);
        float4 q0 = cw4[0], q1 = cw4[1], q2 = cw4[2], q3 = cw4[3], q4 = cw4[4];
        w[0][0]=q0.x; w[0][1]=q0.y; w[0][2]=q0.z; w[0][3]=q0.w; w[0][4]=q1.x;
        w[1][0]=q1.y; w[1][1]=q1.z; w[1][2]=q1.w; w[1][3]=q2.x; w[1][4]=q2.y;
        w[2][0]=q2.z; w[2][1]=q2.w; w[2][2]=q3.x; w[2][3]=q3.y; w[2][4]=q3.z;
        w[3][0]=q3.w; w[3][1]=q4.x; w[3][2]=q4.y; w[3][3]=q4.z; w[3][4]=q4.w;
        float4 bb = *reinterpret_cast<const float4*>(conv_b + c0);
        cb[0]=bb.x; cb[1]=bb.y; cb[2]=bb.z; cb[3]=bb.w;
    }

    // ---- warp-private input window (67 floats across lanes in 3 regs) ----
    const long t0w = 2L * (s0 + 32 * wid) - 2;
    float xv0, xv1, xv2;
    {
        const float* xb = x + (long)b * Tn;
        long t = t0w + lane;
        xv0 = (t >= 0 && t < Tn) ? xb[t] : 0.f;
        t += 32;
        xv1 = (t < Tn) ? xb[t] : 0.f;
        t += 32;
        xv2 = (t < Tn) ? xb[t] : 0.f;
    }

    // ---- conv1d + ReLU + fp16 -> own 32-row A tile ----
    {
        const unsigned m = 0xFFFFFFFFu;
        float x0 = __shfl_sync(m, xv0, 0), x1 = __shfl_sync(m, xv0, 1),
              x2 = __shfl_sync(m, xv0, 2), x3 = __shfl_sync(m, xv0, 3),
              x4 = __shfl_sync(m, xv0, 4);
#pragma unroll
        for (int p = 0; p < 32; p++) {
            __half2 vh[2];
#pragma unroll
            for (int j = 0; j < 2; j++) {
                float f0 = fmaf(w[2*j][0], x0, cb[2*j]);
                f0 = fmaf(w[2*j][1], x1, f0);
                f0 = fmaf(w[2*j][2], x2, f0);
                f0 = fmaf(w[2*j][3], x3, f0);
                f0 = fmaf(w[2*j][4], x4, f0);
                f0 = fmaxf(f0, 0.f);
                float f1 = fmaf(w[2*j+1][0], x0, cb[2*j+1]);
                f1 = fmaf(w[2*j+1][1], x1, f1);
                f1 = fmaf(w[2*j+1][2], x2, f1);
                f1 = fmaf(w[2*j+1][3], x3, f1);
                f1 = fmaf(w[2*j+1][4], x4, f1);
                f1 = fmaxf(f1, 0.f);
                vh[j] = __halves2half2(__float2half_rn(f0), __float2half_rn(f1));
            }
            *reinterpret_cast<uint2*>(fw + p * LDA + c0) =
                *reinterpret_cast<const uint2*>(vh);
            if (p < 31) {
                x0 = x2; x1 = x3; x2 = x4;
                const int i5 = 2 * p + 5, i6 = 2 * p + 6;   // compile-time consts
                x3 = (i5 < 32) ? __shfl_sync(m, xv0, i5)
                   : (i5 < 64) ? __shfl_sync(m, xv1, i5 - 32)
                               : __shfl_sync(m, xv2, i5 - 64);
                x4 = (i6 < 32) ? __shfl_sync(m, xv0, i6)
                   : (i6 < 64) ? __shfl_sync(m, xv1, i6 - 32)
                               : __shfl_sync(m, xv2, i6 - 64);
            }
        }
    }
    __syncwarp();   // STS -> LDSM visibility within the warp

    // ---- GEMM: this warp does m32 x n64 on its own rows ----
    float acc[2][2][4][4];   // [mt][G][nt][q]
#pragma unroll
    for (int mt = 0; mt < 2; mt++)
#pragma unroll
        for (int G = 0; G < 2; G++)
#pragma unroll
            for (int nt = 0; nt < 4; nt++)
#pragma unroll
                for (int qq = 0; qq < 4; qq++) acc[mt][G][nt][qq] = 0.f;

    const int aoff0 = (lane & 15) * LDA + ((lane >> 4) << 3);
    const uint32_t a_s0 = smem_u32(fw + aoff0);
    const uint32_t a_s1 = smem_u32(fw + aoff0 + 16 * LDA);

#pragma unroll
    for (int c = 0; c < 8; c++) {
        const uint32_t kB = c * 32;
        uint32_t ah[2][4];
        LDSM_X4(ah[0][0], ah[0][1], ah[0][2], ah[0][3], a_s0 + kB);
        LDSM_X4(ah[1][0], ah[1][1], ah[1][2], ah[1][3], a_s1 + kB);

#pragma unroll
        for (int G = 0; G < 2; G++) {
            const uint4* bp = g_bfrag + (G * 8 + c) * 2 * 32 + lane;
            const uint4 v0 = __ldg(bp);
            const uint4 v1 = __ldg(bp + 32);
            const uint32_t bh[2][4] = {{v0.x, v0.y, v0.z, v0.w},
                                       {v1.x, v1.y, v1.z, v1.w}};
#pragma unroll
            for (int mt = 0; mt < 2; mt++) {
#pragma unroll
                for (int np = 0; np < 2; np++) {
                    MMA16816(acc[mt][G][2*np+0], ah[mt][0], ah[mt][1], ah[mt][2], ah[mt][3],
                             bh[np][0], bh[np][1]);
                    MMA16816(acc[mt][G][2*np+1], ah[mt][0], ah[mt][1], ah[mt][2], ah[mt][3],
                             bh[np][2], bh[np][3]);
                }
            }
        }
    }

    // ---- epilogue: 8 consecutive cols per (row, G) -> STG.128 ----
    const int gid = lane >> 2, tig = lane & 3;
    float bb[2][8];
#pragma unroll
    for (int G = 0; G < 2; G++) {
        const int colb = 32 * G + tig * 8;
        const float4 b0 = __ldg(reinterpret_cast<const float4*>(lin_b + colb));
        const float4 b1 = __ldg(reinterpret_cast<const float4*>(lin_b + colb + 4));
        bb[G][0]=b0.x; bb[G][1]=b0.y; bb[G][2]=b0.z; bb[G][3]=b0.w;
        bb[G][4]=b1.x; bb[G][5]=b1.y; bb[G][6]=b1.z; bb[G][7]=b1.w;
    }
#pragma unroll
    for (int mt = 0; mt < 2; mt++) {
        const int row = s0 + 32 * wid + mt * 16 + gid;
        float* ob = out + ((long)b * Sn + row) * Pn;
#pragma unroll
        for (int G = 0; G < 2; G++) {
            float* obg = ob + 32 * G + tig * 8;
            float4 r0a = make_float4(acc[mt][G][0][0]+bb[G][0], acc[mt][G][0][1]+bb[G][1],
                                     acc[mt][G][1][0]+bb[G][2], acc[mt][G][1][1]+bb[G][3]);
            float4 r0b = make_float4(acc[mt][G][2][0]+bb[G][4], acc[mt][G][2][1]+bb[G][5],
                                     acc[mt][G][3][0]+bb[G][6], acc[mt][G][3][1]+bb[G][7]);
            float4 r1a = make_float4(acc[mt][G][0][2]+bb[G][0], acc[mt][G][0][3]+bb[G][1],
                                     acc[mt][G][1][2]+bb[G][2], acc[mt][G][1][3]+bb[G][3]);
            float4 r1b = make_float4(acc[mt][G][2][2]+bb[G][4], acc[mt][G][2][3]+bb[G][5],
                                     acc[mt][G][3][2]+bb[G][6], acc[mt][G][3][3]+bb[G][7]);
            *reinterpret_cast<float4*>(obg)              = r0a;
            *reinterpret_cast<float4*>(obg + 4)          = r0b;
            *reinterpret_cast<float4*>(obg + 8 * Pn)     = r1a;
            *reinterpret_cast<float4*>(obg + 8 * Pn + 4) = r1b;
        }
    }
}

extern "C" void kernel_launch(void* const* d_in, const int* in_sizes, int n_in,
                              void* d_out, int out_size) {
    (void)in_sizes; (void)n_in; (void)out_size;
    const float* x      = (const float*)d_in[0];
    const float* conv_w = (const float*)d_in[1];
    const float* conv_b = (const float*)d_in[2];
    const float* lin_w  = (const float*)d_in[3];
    const float* lin_b  = (const float*)d_in[4];
    float* out = (float*)d_out;

    pack_w_kernel<<<2, 256>>>(lin_w);

    cudaFuncSetAttribute(encoder_kernel,
                         cudaFuncAttributeMaxDynamicSharedMemorySize, SMEM_TOTAL);
    dim3 grid((unsigned)(Sn / S_TILE), Bn);
    encoder_kernel<<<grid, THREADS, SMEM_TOTAL>>>(x, conv_w, conv_b, lin_b, out);
}